// round 14
// baseline (speedup 1.0000x reference)
#include <cuda_runtime.h>
#include <cuda_bf16.h>
#include <cuda_fp16.h>
#include <cstdint>

#define DEV_INLINE __device__ __forceinline__

// ---------------- problem dims (fixed by reference) ----------------
constexpr int M_TOK = 8 * 2048;   // 16384 tokens
constexpr int NE    = 1024;       // n_embd
constexpr int DFF   = 4096;       // 4*n_embd
constexpr int RANK  = 4;
constexpr float LORA_SCALE = 0.25f;

// ---------------- device scratch (allocation-free rule: __device__ globals) ----------------
__device__ __half g_xf[(size_t)M_TOK * NE];
__device__ __half g_w1f[(size_t)DFF * NE];
__device__ __half g_w2f[(size_t)NE * DFF];
__device__ __half g_hf[(size_t)M_TOK * DFF];
__device__ __align__(16) float g_t1[(size_t)M_TOK * RANK];
__device__ __align__(16) float g_t2[(size_t)M_TOK * RANK];

// ---------------- PTX helpers (family-portable: cp.async, ldmatrix, mma.sync) ----------------
DEV_INLINE uint32_t smem_u32(const void* p) {
    uint32_t a;
    asm("{ .reg .u64 t; cvta.to.shared.u64 t, %1; cvt.u32.u64 %0, t; }" : "=r"(a) : "l"(p));
    return a;
}

#define CP_ASYNC16(dst, src) \
    asm volatile("cp.async.cg.shared.global [%0], [%1], 16;" :: "r"(dst), "l"(src))
#define CP_COMMIT() asm volatile("cp.async.commit_group;" ::: "memory")

template <int N>
DEV_INLINE void cp_wait() { asm volatile("cp.async.wait_group %0;" :: "n"(N) : "memory"); }

DEV_INLINE void ldsm_x4(uint32_t r[4], uint32_t addr) {
    asm volatile("ldmatrix.sync.aligned.m8n8.x4.shared.b16 {%0,%1,%2,%3}, [%4];"
                 : "=r"(r[0]), "=r"(r[1]), "=r"(r[2]), "=r"(r[3]) : "r"(addr));
}

DEV_INLINE void mma_f16(float c[4], const uint32_t a[4], const uint32_t* b) {
    asm volatile(
        "mma.sync.aligned.m16n8k16.row.col.f32.f16.f16.f32 "
        "{%0,%1,%2,%3}, {%4,%5,%6,%7}, {%8,%9}, {%0,%1,%2,%3};"
        : "+f"(c[0]), "+f"(c[1]), "+f"(c[2]), "+f"(c[3])
        : "r"(a[0]), "r"(a[1]), "r"(a[2]), "r"(a[3]), "r"(b[0]), "r"(b[1]));
}

// ---------------- GEMM config ----------------
// CTA tile 128x128, warp grid 2x4, warp tile 64x32, BK=64, 3 stages, 2 CTAs/SM,
// persistent CTAs with cross-tile pipeline continuity.
constexpr int BM = 128, BN = 128, BK = 64, STAGES = 3;
constexpr int ROWB     = BK * 2;                 // 128 bytes per swizzled row
constexpr int A_TILE_B = BM * ROWB;              // 16 KB
constexpr int B_TILE_B = BN * ROWB;              // 16 KB
constexpr int STAGE_B  = A_TILE_B + B_TILE_B;    // 32 KB
constexpr int SBL_B    = BN * RANK * 4;          // 2 KB per LoRA buffer
constexpr int SMEM_TOT = STAGES * STAGE_B + 2 * SBL_B;  // 100 KB -> 2 CTAs/SM
constexpr int MT_TILES = M_TOK / BM;             // 128 (power of two)
constexpr int NPERSIST = 2 * 148;                // one full wave at occ 2

// Load a 128x64 fp16 tile into XOR-crosswise swizzled SMEM (16B granule c16 at
// column c16 ^ (row & 7)). Conflict-free for stores and ldmatrix.
DEV_INLINE void load_tile(uint32_t sdst, const __half* g, int r0, int kc,
                          int ldK, int tid) {
    const char* gb = reinterpret_cast<const char*>(g);
#pragma unroll
    for (int i = 0; i < 4; ++i) {
        int gidx = tid + i * 256;
        int row = gidx >> 3;
        int c16 = gidx & 7;
        uint32_t dst = sdst + row * ROWB + ((c16 ^ (row & 7)) << 4);
        const char* src = gb + ((size_t)(r0 + row) * ldK + kc + c16 * 8) * 2;
        CP_ASYNC16(dst, src);
    }
}

DEV_INLINE void load_stage(uint32_t sp, const __half* A, const __half* Bw,
                           int m0, int n0, int kc, int K, int tid) {
    load_tile(sp, A, m0, kc, K, tid);
    load_tile(sp + A_TILE_B, Bw, n0, kc, K, tid);
}

// ---------------- persistent fused GEMM: D = A*B^T (fp16) + LoRA ----------------
// RELU_F16 ? (relu + write fp16) : (write fp32)
template <int K_T, int NTOT_T, bool RELU_F16>
__global__ void __launch_bounds__(256, 2)
gemm_hmma_kernel(const __half* __restrict__ A, const __half* __restrict__ Bw,
                 const float* __restrict__ t_vec,       // [M_TOK, RANK]
                 const float* __restrict__ Blora_base,  // [NUM_LOOPS, NTOT_T, RANK]
                 const int* __restrict__ id_ptr,
                 __half* __restrict__ Oh, float* __restrict__ Of) {
    constexpr int NC   = K_T / BK;
    constexpr int TTOT = MT_TILES * (NTOT_T / BN);

    extern __shared__ char smem[];
    const uint32_t sbase = smem_u32(smem);
    float* sBl0 = reinterpret_cast<float*>(smem + STAGES * STAGE_B);

    const int tid  = threadIdx.x;
    const int lane = tid & 31;
    const int warp = tid >> 5;
    const int wm = warp >> 2;   // 0..1 : warp m-tile (64 rows)
    const int wn = warp & 3;    // 0..3 : warp n-tile (32 cols)
    const int bid = blockIdx.x;

    const int nMine = (TTOT - bid + NPERSIST - 1) / NPERSIST;
    const int id = *id_ptr;
    const float* BlAll = Blora_base + (size_t)id * NTOT_T * RANK;

    // current + next tile coordinates
    int tau  = bid;
    int m0   = (tau & (MT_TILES - 1)) * BM;
    int n0   = (tau >> 7) * BN;
    int tauN = bid + NPERSIST;
    int m0n  = (tauN & (MT_TILES - 1)) * BM;
    int n0n  = (tauN >> 7) * BN;

    float acc[4][4][4];
#pragma unroll
    for (int i = 0; i < 4; ++i)
#pragma unroll
        for (int j = 0; j < 4; ++j)
#pragma unroll
            for (int e = 0; e < 4; ++e) acc[i][j][e] = 0.0f;

    // one-time prologue: chunks 0,1 of first tile -> stages 0,1
    load_stage(sbase + 0 * STAGE_B, A, Bw, m0, n0, 0 * BK, K_T, tid);
    CP_COMMIT();
    load_stage(sbase + 1 * STAGE_B, A, Bw, m0, n0, 1 * BK, K_T, tid);
    CP_COMMIT();

    // per-thread fragment address components (XOR swizzle)
    const int arow = wm * 64 + (lane & 15);                       // A: ldmatrix x4 rows
    const int brow = wn * 32 + ((lane >> 4) << 3) + (lane & 7);   // B: two n8 tiles per x4
    const int swA  = (lane & 15) & 7;
    const int swB  = lane & 7;

    int sidx = 0;                              // stage of current chunk (g % 3)
    const int lastJ = nMine - 1;

    for (int j = 0; j < nMine; ++j) {
        const bool lastTile = (j == lastJ);
        for (int c = 0; c < NC; ++c) {
            if (lastTile && c == NC - 1) { cp_wait<0>(); }
            else                         { cp_wait<1>(); }
            __syncthreads();   // data for chunk visible AND all warps past prior chunk

            // stage this tile's LoRA B columns once (dedicated buffer, double-buffered)
            if (c == 0) {
                float* dstB = sBl0 + (j & 1) * (BN * RANK);
                const float* srcB = BlAll + (size_t)n0 * RANK;
#pragma unroll
                for (int i = 0; i < 2; ++i) dstB[tid + i * 256] = srcB[tid + i * 256];
            }

            const uint32_t st  = sbase + sidx * STAGE_B;
            const uint32_t stA = st + arow * ROWB;
            const uint32_t stB = st + A_TILE_B + brow * ROWB;

#pragma unroll
            for (int ks = 0; ks < 4; ++ks) {   // 4 x k16 per 64-K chunk
                const uint32_t axo = (uint32_t)(((ks * 2 + (lane >> 4)) ^ swA) << 4);
                const uint32_t bxo = (uint32_t)(((ks * 2 + ((lane >> 3) & 1)) ^ swB) << 4);

                uint32_t af[4][4], bf[2][4];
#pragma unroll
                for (int mt = 0; mt < 4; ++mt) ldsm_x4(af[mt], stA + mt * 16 * ROWB + axo);
#pragma unroll
                for (int np = 0; np < 2; ++np) ldsm_x4(bf[np], stB + np * 16 * ROWB + bxo);

#pragma unroll
                for (int mt = 0; mt < 4; ++mt) {
#pragma unroll
                    for (int nt = 0; nt < 4; ++nt) {
                        mma_f16(acc[mt][nt], af[mt], &bf[nt >> 1][(nt & 1) * 2]);
                    }
                }
            }

            // refill chunk g+2 (may belong to the NEXT tile -> pipeline never drains)
            {
                const int sR = (sidx == 0) ? 2 : sidx - 1;   // (g+2) % 3
                const uint32_t sp = sbase + sR * STAGE_B;
                const int cr = c + 2;
                if (cr < NC) {
                    load_stage(sp, A, Bw, m0, n0, cr * BK, K_T, tid);
                    CP_COMMIT();
                } else if (!lastTile) {
                    load_stage(sp, A, Bw, m0n, n0n, (cr - NC) * BK, K_T, tid);
                    CP_COMMIT();
                }
            }
            sidx = (sidx == 2) ? 0 : sidx + 1;

            // ---- per-tile epilogue: acc + LoRA(t * B^T) * scale ----
            if (c == NC - 1) {
                const float* sBl = sBl0 + (j & 1) * (BN * RANK);
#pragma unroll
                for (int mt = 0; mt < 4; ++mt) {
#pragma unroll
                    for (int half = 0; half < 2; ++half) {
                        const int row = m0 + wm * 64 + mt * 16 + (lane >> 2) + half * 8;
                        const float4 tr =
                            *reinterpret_cast<const float4*>(t_vec + (size_t)row * RANK);
#pragma unroll
                        for (int nt = 0; nt < 4; ++nt) {
                            const int coll = wn * 32 + nt * 8 + (lane & 3) * 2;
                            float v[2];
#pragma unroll
                            for (int e = 0; e < 2; ++e) {
                                const float* b4 = sBl + (coll + e) * RANK;
                                float d = fmaf(tr.x, b4[0], fmaf(tr.y, b4[1],
                                          fmaf(tr.z, b4[2], tr.w * b4[3])));
                                v[e] = acc[mt][nt][half * 2 + e] + LORA_SCALE * d;
                            }
                            const size_t o = (size_t)row * NTOT_T + n0 + coll;
                            if (RELU_F16) {
                                __half2 hv;
                                hv.x = __float2half(fmaxf(v[0], 0.0f));
                                hv.y = __float2half(fmaxf(v[1], 0.0f));
                                *reinterpret_cast<__half2*>(Oh + o) = hv;
                            } else {
                                *reinterpret_cast<float2*>(Of + o) = make_float2(v[0], v[1]);
                            }
                        }
                    }
                }
                // reset accumulators for the next tile
#pragma unroll
                for (int i = 0; i < 4; ++i)
#pragma unroll
                    for (int jj = 0; jj < 4; ++jj)
#pragma unroll
                        for (int e = 0; e < 4; ++e) acc[i][jj][e] = 0.0f;
            }
        }
        // advance tiles
        tau  = tauN;  m0 = m0n;  n0 = n0n;
        tauN = tau + NPERSIST;
        m0n  = (tauN & (MT_TILES - 1)) * BM;
        n0n  = (tauN >> 7) * BN;
    }
}

// ---------------- fp32 -> fp16 convert (for weights) ----------------
__global__ void cvt_kernel(const float* __restrict__ src, __half* __restrict__ dst, int n) {
    int i = blockIdx.x * blockDim.x + threadIdx.x;
    const int stride = gridDim.x * blockDim.x;
    for (; i * 4 + 3 < n; i += stride) {
        float4 v = *reinterpret_cast<const float4*>(src + i * 4);
        __half2 a = __floats2half2_rn(v.x, v.y);
        __half2 b = __floats2half2_rn(v.z, v.w);
        *reinterpret_cast<uint2*>(dst + i * 4) =
            make_uint2(*reinterpret_cast<uint32_t*>(&a), *reinterpret_cast<uint32_t*>(&b));
    }
}

// ---------------- fused: t1 = x @ A1[id]^T AND xf = fp16(x). One block per row. ----------------
__global__ void __launch_bounds__(128)
tvec_x_kernel(const float* __restrict__ X, const float* __restrict__ Afull,
              const int* __restrict__ idp, float* __restrict__ T,
              __half* __restrict__ Xf) {
    const int m = blockIdx.x;
    const int tid = threadIdx.x;
    const float* Aa = Afull + (size_t)(*idp) * RANK * NE;
    const float* xr = X + (size_t)m * NE + tid * 8;     // 8 contiguous floats/thread

    float4 v0 = *reinterpret_cast<const float4*>(xr);
    float4 v1 = *reinterpret_cast<const float4*>(xr + 4);

    // fp16 store (coalesced 16B per thread)
    {
        __half2 a = __floats2half2_rn(v0.x, v0.y);
        __half2 b = __floats2half2_rn(v0.z, v0.w);
        __half2 cc = __floats2half2_rn(v1.x, v1.y);
        __half2 dd = __floats2half2_rn(v1.z, v1.w);
        *reinterpret_cast<uint4*>(Xf + (size_t)m * NE + tid * 8) =
            make_uint4(*reinterpret_cast<uint32_t*>(&a), *reinterpret_cast<uint32_t*>(&b),
                       *reinterpret_cast<uint32_t*>(&cc), *reinterpret_cast<uint32_t*>(&dd));
    }

    float s[4];
#pragma unroll
    for (int r = 0; r < RANK; ++r) {
        const float* ar = Aa + (size_t)r * NE + tid * 8;
        float4 a0 = *reinterpret_cast<const float4*>(ar);
        float4 a1 = *reinterpret_cast<const float4*>(ar + 4);
        s[r] = v0.x * a0.x + v0.y * a0.y + v0.z * a0.z + v0.w * a0.w
             + v1.x * a1.x + v1.y * a1.y + v1.z * a1.z + v1.w * a1.w;
    }
#pragma unroll
    for (int o = 16; o > 0; o >>= 1) {
#pragma unroll
        for (int r = 0; r < RANK; ++r) s[r] += __shfl_xor_sync(0xffffffffu, s[r], o);
    }
    __shared__ float red[4][4];
    const int wid = tid >> 5, lane = tid & 31;
    if (lane == 0) {
#pragma unroll
        for (int r = 0; r < RANK; ++r) red[wid][r] = s[r];
    }
    __syncthreads();
    if (tid < 4) T[(size_t)m * RANK + tid] = red[0][tid] + red[1][tid] + red[2][tid] + red[3][tid];
}

// ---------------- t2 = h @ A2[id]^T (fp16 h). One block of 256 per row, single pass. ----------------
__global__ void __launch_bounds__(256)
tvec_h_kernel(const __half* __restrict__ H, const float* __restrict__ Afull,
              const int* __restrict__ idp, float* __restrict__ T) {
    const int m = blockIdx.x;
    const int tid = threadIdx.x;
    const float* Aa = Afull + (size_t)(*idp) * RANK * DFF;
    const int idx = tid * 16;                           // 16 contiguous halves/thread

    uint4 pk0 = *reinterpret_cast<const uint4*>(H + (size_t)m * DFF + idx);
    uint4 pk1 = *reinterpret_cast<const uint4*>(H + (size_t)m * DFF + idx + 8);

    float vx[16];
    {
        const __half2* h2 = reinterpret_cast<const __half2*>(&pk0);
#pragma unroll
        for (int p = 0; p < 4; ++p) {
            float2 f = __half22float2(h2[p]);
            vx[p * 2] = f.x; vx[p * 2 + 1] = f.y;
        }
        h2 = reinterpret_cast<const __half2*>(&pk1);
#pragma unroll
        for (int p = 0; p < 4; ++p) {
            float2 f = __half22float2(h2[p]);
            vx[8 + p * 2] = f.x; vx[8 + p * 2 + 1] = f.y;
        }
    }

    float s[4];
#pragma unroll
    for (int r = 0; r < RANK; ++r) {
        const float* ar = Aa + (size_t)r * DFF + idx;
        float acc = 0.f;
#pragma unroll
        for (int q = 0; q < 4; ++q) {
            float4 a = *reinterpret_cast<const float4*>(ar + q * 4);
            acc += vx[q * 4] * a.x + vx[q * 4 + 1] * a.y
                 + vx[q * 4 + 2] * a.z + vx[q * 4 + 3] * a.w;
        }
        s[r] = acc;
    }
#pragma unroll
    for (int o = 16; o > 0; o >>= 1) {
#pragma unroll
        for (int r = 0; r < RANK; ++r) s[r] += __shfl_xor_sync(0xffffffffu, s[r], o);
    }
    __shared__ float red[8][4];
    const int wid = tid >> 5, lane = tid & 31;
    if (lane == 0) {
#pragma unroll
        for (int r = 0; r < RANK; ++r) red[wid][r] = s[r];
    }
    __syncthreads();
    if (tid < 4) {
        float acc = 0.f;
#pragma unroll
        for (int w = 0; w < 8; ++w) acc += red[w][tid];
        T[(size_t)m * RANK + tid] = acc;
    }
}

// ---------------- launch ----------------
extern "C" void kernel_launch(void* const* d_in, const int* in_sizes, int n_in,
                              void* d_out, int out_size) {
    (void)in_sizes; (void)n_in; (void)out_size;
    const float* x  = (const float*)d_in[0];
    const float* W1 = (const float*)d_in[1];
    const float* A1 = (const float*)d_in[2];
    const float* B1 = (const float*)d_in[3];
    const float* W2 = (const float*)d_in[4];
    const float* A2 = (const float*)d_in[5];
    const float* B2 = (const float*)d_in[6];
    const int*   id = (const int*)d_in[7];
    float* out = (float*)d_out;

    __half *xf, *w1f, *w2f, *hf;
    float *t1, *t2;
    cudaGetSymbolAddress((void**)&xf,  g_xf);
    cudaGetSymbolAddress((void**)&w1f, g_w1f);
    cudaGetSymbolAddress((void**)&w2f, g_w2f);
    cudaGetSymbolAddress((void**)&hf,  g_hf);
    cudaGetSymbolAddress((void**)&t1,  g_t1);
    cudaGetSymbolAddress((void**)&t2,  g_t2);

    cudaFuncSetAttribute((const void*)gemm_hmma_kernel<NE, DFF, true>,
                         cudaFuncAttributeMaxDynamicSharedMemorySize, SMEM_TOT);
    cudaFuncSetAttribute((const void*)gemm_hmma_kernel<DFF, NE, false>,
                         cudaFuncAttributeMaxDynamicSharedMemorySize, SMEM_TOT);

    // weight converts
    cvt_kernel<<<2048, 256>>>(W1, w1f, DFF * NE);
    cvt_kernel<<<2048, 256>>>(W2, w2f, NE * DFF);

    // t1 = x @ A1[id]^T fused with xf = fp16(x)
    tvec_x_kernel<<<M_TOK, 128>>>(x, A1, id, t1, xf);

    // h = relu(x W1^T + t1 B1^T * s), stored fp16  (persistent, K=1024, N=4096)
    gemm_hmma_kernel<NE, DFF, true><<<NPERSIST, 256, SMEM_TOT>>>(
        xf, w1f, t1, B1, id, hf, nullptr);

    // t2 = h @ A2[id]^T
    tvec_h_kernel<<<M_TOK, 256>>>(hf, A2, id, t2);

    // out = h W2^T + t2 B2^T * s  (fp32)           (persistent, K=4096, N=1024)
    gemm_hmma_kernel<DFF, NE, false><<<NPERSIST, 256, SMEM_TOT>>>(
        hf, w2f, t2, B2, id, nullptr, out);
}

// round 16
// speedup vs baseline: 1.1136x; 1.1136x over previous
#include <cuda_runtime.h>
#include <cuda_bf16.h>
#include <cuda_fp16.h>
#include <cstdint>

#define DEV_INLINE __device__ __forceinline__

// ---------------- problem dims (fixed by reference) ----------------
constexpr int M_TOK = 8 * 2048;   // 16384 tokens
constexpr int NE    = 1024;       // n_embd
constexpr int DFF   = 4096;       // 4*n_embd
constexpr int RANK  = 4;
constexpr float LORA_SCALE = 0.25f;

// ---------------- device scratch (allocation-free rule: __device__ globals) ----------------
__device__ __half g_xf[(size_t)M_TOK * NE];
__device__ __half g_w1f[(size_t)DFF * NE];
__device__ __half g_w2f[(size_t)NE * DFF];
__device__ __half g_hf[(size_t)M_TOK * DFF];
__device__ __align__(16) float g_t1[(size_t)M_TOK * RANK];
__device__ __align__(16) float g_t2[(size_t)M_TOK * RANK];

// ---------------- PTX helpers (family-portable: cp.async, ldmatrix, mma.sync) ----------------
DEV_INLINE uint32_t smem_u32(const void* p) {
    uint32_t a;
    asm("{ .reg .u64 t; cvta.to.shared.u64 t, %1; cvt.u32.u64 %0, t; }" : "=r"(a) : "l"(p));
    return a;
}

#define CP_ASYNC16(dst, src) \
    asm volatile("cp.async.cg.shared.global [%0], [%1], 16;" :: "r"(dst), "l"(src))
#define CP_COMMIT() asm volatile("cp.async.commit_group;" ::: "memory")

template <int N>
DEV_INLINE void cp_wait() { asm volatile("cp.async.wait_group %0;" :: "n"(N) : "memory"); }

DEV_INLINE void ldsm_x4(uint32_t r[4], uint32_t addr) {
    asm volatile("ldmatrix.sync.aligned.m8n8.x4.shared.b16 {%0,%1,%2,%3}, [%4];"
                 : "=r"(r[0]), "=r"(r[1]), "=r"(r[2]), "=r"(r[3]) : "r"(addr));
}

DEV_INLINE void mma_f16(float c[4], const uint32_t a[4], const uint32_t* b) {
    asm volatile(
        "mma.sync.aligned.m16n8k16.row.col.f32.f16.f16.f32 "
        "{%0,%1,%2,%3}, {%4,%5,%6,%7}, {%8,%9}, {%0,%1,%2,%3};"
        : "+f"(c[0]), "+f"(c[1]), "+f"(c[2]), "+f"(c[3])
        : "r"(a[0]), "r"(a[1]), "r"(a[2]), "r"(a[3]), "r"(b[0]), "r"(b[1]));
}

// ---------------- GEMM config ----------------
// CTA tile 128x128, 128 threads (4 warps), warp grid 2x2, WARP TILE 64x64,
// BK=64, 3 stages, 2 CTAs/SM. Rationale: smem-crossbar traffic drops to
// 0.094 B/MAC (96 B/cyc at full HMMA rate) vs 0.125 (=128 B/cyc, the crossbar
// ceiling) for 64x32 warp tiles; 128-thread CTAs keep 256 regs/thread at occ 2.
constexpr int BM = 128, BN = 128, BK = 64, STAGES = 3;
constexpr int NTHREADS  = 128;
constexpr int ROWB     = BK * 2;                 // 128 bytes per swizzled row
constexpr int A_TILE_B = BM * ROWB;              // 16 KB
constexpr int B_TILE_B = BN * ROWB;              // 16 KB
constexpr int STAGE_B  = A_TILE_B + B_TILE_B;    // 32 KB
constexpr int SMEM_GEMM = STAGES * STAGE_B;      // 96 KB -> 2 CTAs/SM

// Load a ROWS x 64 fp16 tile into XOR-crosswise swizzled SMEM (16B granule c16 at
// column c16 ^ (row & 7)). Conflict-free for stores and ldmatrix.
template <int ROWS>
DEV_INLINE void load_tile(uint32_t sdst, const __half* g, int r0, int kc,
                          int ldK, int tid) {
    const char* gb = reinterpret_cast<const char*>(g);
#pragma unroll
    for (int i = 0; i < ROWS * 8 / NTHREADS; ++i) {
        int gidx = tid + i * NTHREADS;
        int row = gidx >> 3;
        int c16 = gidx & 7;
        uint32_t dst = sdst + row * ROWB + ((c16 ^ (row & 7)) << 4);
        const char* src = gb + ((size_t)(r0 + row) * ldK + kc + c16 * 8) * 2;
        CP_ASYNC16(dst, src);
    }
}

// ---------------- fused GEMM: D = A*B^T (fp16) + LoRA ----------------
// RELU_F16 ? (relu + write fp16) : (write fp32)
template <bool RELU_F16>
__global__ void __launch_bounds__(NTHREADS, 2)
gemm_hmma_kernel(const __half* __restrict__ A, const __half* __restrict__ Bw,
                 int K, int Ntot,
                 const float* __restrict__ t_vec,       // [M_TOK, RANK]
                 const float* __restrict__ Blora_base,  // [NUM_LOOPS, Ntot, RANK]
                 const int* __restrict__ id_ptr,
                 __half* __restrict__ Oh, float* __restrict__ Of) {
    extern __shared__ char smem[];
    const uint32_t sbase = smem_u32(smem);
    const int tid  = threadIdx.x;
    const int lane = tid & 31;
    const int warp = tid >> 5;
    const int wm = warp >> 1;   // 0..1 : warp m-tile (64 rows)
    const int wn = warp & 1;    // 0..1 : warp n-tile (64 cols)

    const int m0 = blockIdx.y * BM;
    const int n0 = blockIdx.x * BN;
    const int NC = K / BK;

    float acc[4][8][4];
#pragma unroll
    for (int i = 0; i < 4; ++i)
#pragma unroll
        for (int j = 0; j < 8; ++j)
#pragma unroll
            for (int e = 0; e < 4; ++e) acc[i][j][e] = 0.0f;

    // prologue: fill STAGES-1 stages
#pragma unroll
    for (int s = 0; s < STAGES - 1; ++s) {
        load_tile<BM>(sbase + s * STAGE_B, A, m0, s * BK, K, tid);
        load_tile<BN>(sbase + s * STAGE_B + A_TILE_B, Bw, n0, s * BK, K, tid);
        CP_COMMIT();
    }

    // per-thread fragment address components (XOR swizzle)
    const int arow = wm * 64 + (lane & 15);                       // A: ldmatrix x4 rows
    const int brow = wn * 64 + ((lane >> 4) << 3) + (lane & 7);   // B: two n8 tiles per x4
    const int swA  = (lane & 15) & 7;
    const int swB  = lane & 7;

    for (int c = 0; c < NC; ++c) {
        // wait until chunk c's group is complete (steady state: STAGES-2 newer in flight)
        if (NC - 1 - c >= STAGES - 2) { cp_wait<STAGES - 2>(); }
        else                          { cp_wait<0>(); }
        __syncthreads();   // single barrier per chunk: data visible AND all warps
                           // finished chunk c-1 (protects the refill below)

        const uint32_t st  = sbase + (c % STAGES) * STAGE_B;
        const uint32_t stA = st + arow * ROWB;
        const uint32_t stB = st + A_TILE_B + brow * ROWB;

#pragma unroll
        for (int ks = 0; ks < 4; ++ks) {   // 4 x k16 per 64-K chunk
            const uint32_t axo = (uint32_t)(((ks * 2 + (lane >> 4)) ^ swA) << 4);
            const uint32_t bxo = (uint32_t)(((ks * 2 + ((lane >> 3) & 1)) ^ swB) << 4);

            uint32_t af[4][4], bf[4][4];
#pragma unroll
            for (int mt = 0; mt < 4; ++mt) ldsm_x4(af[mt], stA + mt * 16 * ROWB + axo);
#pragma unroll
            for (int np = 0; np < 4; ++np) ldsm_x4(bf[np], stB + np * 16 * ROWB + bxo);

#pragma unroll
            for (int mt = 0; mt < 4; ++mt) {
#pragma unroll
                for (int nt = 0; nt < 8; ++nt) {
                    mma_f16(acc[mt][nt], af[mt], &bf[nt >> 1][(nt & 1) * 2]);
                }
            }
        }

        // refill: stage (c+S-1)%S == (c-1)%S, consumed at iter c-1; every warp
        // passed this iteration's barrier after finishing iter c-1 -> safe.
        const int pre = c + STAGES - 1;
        if (pre < NC) {
            const uint32_t sp = sbase + (pre % STAGES) * STAGE_B;
            load_tile<BM>(sp, A, m0, pre * BK, K, tid);
            load_tile<BN>(sp + A_TILE_B, Bw, n0, pre * BK, K, tid);
            CP_COMMIT();
        }
    }

    // ---- epilogue: acc + LoRA(t * B^T) * scale ----
    __syncthreads();   // all warps done reading the last stage (may be stage 0)
    float* sBl = reinterpret_cast<float*>(smem);   // [BN][RANK]
    {
        const int id = *id_ptr;
        const float* Bl2 = Blora_base + (size_t)id * Ntot * RANK + (size_t)n0 * RANK;
        for (int i = tid; i < BN * RANK; i += NTHREADS) sBl[i] = Bl2[i];
    }
    __syncthreads();

#pragma unroll
    for (int mt = 0; mt < 4; ++mt) {
#pragma unroll
        for (int half = 0; half < 2; ++half) {
            const int row = m0 + wm * 64 + mt * 16 + (lane >> 2) + half * 8;
            const float4 tr = *reinterpret_cast<const float4*>(t_vec + (size_t)row * RANK);
#pragma unroll
            for (int nt = 0; nt < 8; ++nt) {
                const int coll = wn * 64 + nt * 8 + (lane & 3) * 2;  // local col in [0,BN)
                float v[2];
#pragma unroll
                for (int e = 0; e < 2; ++e) {
                    const float* b4 = sBl + (coll + e) * RANK;
                    float d = fmaf(tr.x, b4[0], fmaf(tr.y, b4[1],
                              fmaf(tr.z, b4[2], tr.w * b4[3])));
                    v[e] = acc[mt][nt][half * 2 + e] + LORA_SCALE * d;
                }
                const size_t o = (size_t)row * Ntot + n0 + coll;
                if (RELU_F16) {
                    __half2 hv;
                    hv.x = __float2half(fmaxf(v[0], 0.0f));
                    hv.y = __float2half(fmaxf(v[1], 0.0f));
                    *reinterpret_cast<__half2*>(Oh + o) = hv;
                } else {
                    *reinterpret_cast<float2*>(Of + o) = make_float2(v[0], v[1]);
                }
            }
        }
    }
}

// ---------------- fp32 -> fp16 convert (for weights) ----------------
__global__ void cvt_kernel(const float* __restrict__ src, __half* __restrict__ dst, int n) {
    int i = blockIdx.x * blockDim.x + threadIdx.x;
    const int stride = gridDim.x * blockDim.x;
    for (; i * 4 + 3 < n; i += stride) {
        float4 v = *reinterpret_cast<const float4*>(src + i * 4);
        __half2 a = __floats2half2_rn(v.x, v.y);
        __half2 b = __floats2half2_rn(v.z, v.w);
        *reinterpret_cast<uint2*>(dst + i * 4) =
            make_uint2(*reinterpret_cast<uint32_t*>(&a), *reinterpret_cast<uint32_t*>(&b));
    }
}

// ---------------- fused: t1 = x @ A1[id]^T AND xf = fp16(x). One block per row. ----------------
__global__ void __launch_bounds__(128)
tvec_x_kernel(const float* __restrict__ X, const float* __restrict__ Afull,
              const int* __restrict__ idp, float* __restrict__ T,
              __half* __restrict__ Xf) {
    const int m = blockIdx.x;
    const int tid = threadIdx.x;
    const float* Aa = Afull + (size_t)(*idp) * RANK * NE;
    const float* xr = X + (size_t)m * NE + tid * 8;     // 8 contiguous floats/thread

    float4 v0 = *reinterpret_cast<const float4*>(xr);
    float4 v1 = *reinterpret_cast<const float4*>(xr + 4);

    // fp16 store (coalesced 16B per thread)
    {
        __half2 a = __floats2half2_rn(v0.x, v0.y);
        __half2 b = __floats2half2_rn(v0.z, v0.w);
        __half2 cc = __floats2half2_rn(v1.x, v1.y);
        __half2 dd = __floats2half2_rn(v1.z, v1.w);
        *reinterpret_cast<uint4*>(Xf + (size_t)m * NE + tid * 8) =
            make_uint4(*reinterpret_cast<uint32_t*>(&a), *reinterpret_cast<uint32_t*>(&b),
                       *reinterpret_cast<uint32_t*>(&cc), *reinterpret_cast<uint32_t*>(&dd));
    }

    float s[4];
#pragma unroll
    for (int r = 0; r < RANK; ++r) {
        const float* ar = Aa + (size_t)r * NE + tid * 8;
        float4 a0 = *reinterpret_cast<const float4*>(ar);
        float4 a1 = *reinterpret_cast<const float4*>(ar + 4);
        s[r] = v0.x * a0.x + v0.y * a0.y + v0.z * a0.z + v0.w * a0.w
             + v1.x * a1.x + v1.y * a1.y + v1.z * a1.z + v1.w * a1.w;
    }
#pragma unroll
    for (int o = 16; o > 0; o >>= 1) {
#pragma unroll
        for (int r = 0; r < RANK; ++r) s[r] += __shfl_xor_sync(0xffffffffu, s[r], o);
    }
    __shared__ float red[4][4];
    const int wid = tid >> 5, lane = tid & 31;
    if (lane == 0) {
#pragma unroll
        for (int r = 0; r < RANK; ++r) red[wid][r] = s[r];
    }
    __syncthreads();
    if (tid < 4) T[(size_t)m * RANK + tid] = red[0][tid] + red[1][tid] + red[2][tid] + red[3][tid];
}

// ---------------- t2 = h @ A2[id]^T (fp16 h). One block of 256 per row, single pass. ----------------
__global__ void __launch_bounds__(256)
tvec_h_kernel(const __half* __restrict__ H, const float* __restrict__ Afull,
              const int* __restrict__ idp, float* __restrict__ T) {
    const int m = blockIdx.x;
    const int tid = threadIdx.x;
    const float* Aa = Afull + (size_t)(*idp) * RANK * DFF;
    const int idx = tid * 16;                           // 16 contiguous halves/thread

    uint4 pk0 = *reinterpret_cast<const uint4*>(H + (size_t)m * DFF + idx);
    uint4 pk1 = *reinterpret_cast<const uint4*>(H + (size_t)m * DFF + idx + 8);

    float vx[16];
    {
        const __half2* h2 = reinterpret_cast<const __half2*>(&pk0);
#pragma unroll
        for (int p = 0; p < 4; ++p) {
            float2 f = __half22float2(h2[p]);
            vx[p * 2] = f.x; vx[p * 2 + 1] = f.y;
        }
        h2 = reinterpret_cast<const __half2*>(&pk1);
#pragma unroll
        for (int p = 0; p < 4; ++p) {
            float2 f = __half22float2(h2[p]);
            vx[8 + p * 2] = f.x; vx[8 + p * 2 + 1] = f.y;
        }
    }

    float s[4];
#pragma unroll
    for (int r = 0; r < RANK; ++r) {
        const float* ar = Aa + (size_t)r * DFF + idx;
        float acc = 0.f;
#pragma unroll
        for (int q = 0; q < 4; ++q) {
            float4 a = *reinterpret_cast<const float4*>(ar + q * 4);
            acc += vx[q * 4] * a.x + vx[q * 4 + 1] * a.y
                 + vx[q * 4 + 2] * a.z + vx[q * 4 + 3] * a.w;
        }
        s[r] = acc;
    }
#pragma unroll
    for (int o = 16; o > 0; o >>= 1) {
#pragma unroll
        for (int r = 0; r < RANK; ++r) s[r] += __shfl_xor_sync(0xffffffffu, s[r], o);
    }
    __shared__ float red[8][4];
    const int wid = tid >> 5, lane = tid & 31;
    if (lane == 0) {
#pragma unroll
        for (int r = 0; r < RANK; ++r) red[wid][r] = s[r];
    }
    __syncthreads();
    if (tid < 4) {
        float acc = 0.f;
#pragma unroll
        for (int w = 0; w < 8; ++w) acc += red[w][tid];
        T[(size_t)m * RANK + tid] = acc;
    }
}

// ---------------- launch ----------------
extern "C" void kernel_launch(void* const* d_in, const int* in_sizes, int n_in,
                              void* d_out, int out_size) {
    (void)in_sizes; (void)n_in; (void)out_size;
    const float* x  = (const float*)d_in[0];
    const float* W1 = (const float*)d_in[1];
    const float* A1 = (const float*)d_in[2];
    const float* B1 = (const float*)d_in[3];
    const float* W2 = (const float*)d_in[4];
    const float* A2 = (const float*)d_in[5];
    const float* B2 = (const float*)d_in[6];
    const int*   id = (const int*)d_in[7];
    float* out = (float*)d_out;

    __half *xf, *w1f, *w2f, *hf;
    float *t1, *t2;
    cudaGetSymbolAddress((void**)&xf,  g_xf);
    cudaGetSymbolAddress((void**)&w1f, g_w1f);
    cudaGetSymbolAddress((void**)&w2f, g_w2f);
    cudaGetSymbolAddress((void**)&hf,  g_hf);
    cudaGetSymbolAddress((void**)&t1,  g_t1);
    cudaGetSymbolAddress((void**)&t2,  g_t2);

    cudaFuncSetAttribute((const void*)gemm_hmma_kernel<true>,
                         cudaFuncAttributeMaxDynamicSharedMemorySize, SMEM_GEMM);
    cudaFuncSetAttribute((const void*)gemm_hmma_kernel<false>,
                         cudaFuncAttributeMaxDynamicSharedMemorySize, SMEM_GEMM);

    // weight converts
    cvt_kernel<<<2048, 256>>>(W1, w1f, DFF * NE);
    cvt_kernel<<<2048, 256>>>(W2, w2f, NE * DFF);

    // t1 = x @ A1[id]^T fused with xf = fp16(x)
    tvec_x_kernel<<<M_TOK, 128>>>(x, A1, id, t1, xf);

    // h = relu(x W1^T + t1 B1^T * s), stored fp16
    gemm_hmma_kernel<true><<<dim3(DFF / BN, M_TOK / BM), NTHREADS, SMEM_GEMM>>>(
        xf, w1f, NE, DFF, t1, B1, id, hf, nullptr);

    // t2 = h @ A2[id]^T
    tvec_h_kernel<<<M_TOK, 256>>>(hf, A2, id, t2);

    // out = h W2^T + t2 B2^T * s  (fp32)
    gemm_hmma_kernel<false><<<dim3(NE / BN, M_TOK / BM), NTHREADS, SMEM_GEMM>>>(
        hf, w2f, DFF, NE, t2, B2, id, nullptr, out);
}